// round 1
// baseline (speedup 1.0000x reference)
#include <cuda_runtime.h>

// DigitCaps fused kernel for GB300 (sm_103a).
// B=128, J=4608, INPUT_D=8, D=8, M=4, C=10, N=J*M=18432.
//
// Pass 1 (caps_kernel): for each (b,j): u[4][8] = x[b,j,:] @ W[j]  (reshaped),
//   winner = argmax_c <u, dc[c]>, accumulate:
//     S[b,d]    += u (all votes)
//     seg[c,d]  += u (winner-gated, per-thread SMEM slices, block-reduced)
//     cnt[c]    += 1 (per-warp SMEM replicas)
// Pass 2 (finish_kernel): dc_new = dc + (seg - cnt*dc)/(B*N);
//   out[b,c] = <S[b], dc_new[c]> / N;  tail = dc_new.

#define J_TOTAL 4608
#define JT 4            // j's per block
#define BT 4            // b's per thread
#define TPB 128
#define WSTR 264        // padded words per j-row of W in smem (conflict-free, 16B-aligned)
#define ASTR 84         // padded per-thread slice stride (80 used, 16B-aligned)
#define NB (J_TOTAL / JT)

__device__ float g_S[1024];   // S[b*8+d]
__device__ float g_seg[80];   // seg[c*8+d]
__device__ float g_cnt[16];   // cnt[c]

__global__ void zero_kernel() {
    int t = blockIdx.x * blockDim.x + threadIdx.x;
    if (t < 1024) g_S[t] = 0.f;
    if (t < 80)   g_seg[t] = 0.f;
    if (t < 16)   g_cnt[t] = 0.f;
}

__global__ __launch_bounds__(TPB) void caps_kernel(
    const float* __restrict__ x,    // [B, J, 8]
    const float* __restrict__ Wg,   // [J, 8, 32]
    const float* __restrict__ dc)   // [10, 8]
{
    __shared__ float Wsh[JT * WSTR];      //  4224 B
    __shared__ float acc[TPB * ASTR];     // 43008 B (per-thread seg slices)
    __shared__ float dcsh[80];
    __shared__ float cntsh[64];           // 4 warps x 16

    const int t   = threadIdx.x;
    const int tj  = t & 3;      // which j within the block
    const int bg  = t >> 2;     // b-group (32 groups x BT=4 b)
    const int wrp = t >> 5;
    const int j   = blockIdx.x * JT + tj;

    // ---- load W tile (4 j's x 256 floats) into padded SMEM ----
    {
        const float4* src = reinterpret_cast<const float4*>(Wg) + (size_t)blockIdx.x * (JT * 64);
        #pragma unroll
        for (int r = 0; r < 2; r++) {
            int g   = t + r * TPB;   // float4 index 0..255
            int jj  = g >> 6;        // 64 float4 per j
            int rem = g & 63;
            *reinterpret_cast<float4*>(&Wsh[jj * WSTR + rem * 4]) = src[g];
        }
    }
    if (t < 80) dcsh[t]  = dc[t];
    if (t < 64) cntsh[t] = 0.f;
    float* myacc = &acc[t * ASTR];
    #pragma unroll
    for (int q = 0; q < 21; q++)
        reinterpret_cast<float4*>(myacc)[q] = make_float4(0.f, 0.f, 0.f, 0.f);
    __syncthreads();

    // ---- load x for my 4 b's (coalesced-ish: 4 lanes cover one 128B chunk) ----
    float xv[BT][8];
    #pragma unroll
    for (int bb = 0; bb < BT; bb++) {
        const float4* xp = reinterpret_cast<const float4*>(
            x + ((size_t)(bg * BT + bb) * J_TOTAL + j) * 8);
        float4 a = xp[0], b4 = xp[1];
        xv[bb][0]=a.x;  xv[bb][1]=a.y;  xv[bb][2]=a.z;  xv[bb][3]=a.w;
        xv[bb][4]=b4.x; xv[bb][5]=b4.y; xv[bb][6]=b4.z; xv[bb][7]=b4.w;
    }

    float sreg[BT][8];
    #pragma unroll
    for (int bb = 0; bb < BT; bb++)
        #pragma unroll
        for (int d = 0; d < 8; d++) sreg[bb][d] = 0.f;

    #pragma unroll
    for (int m = 0; m < 4; m++) {
        // ---- u[bb][d] = sum_i x[bb][i] * W[j][i][m*8+d] ----
        float u[BT][8];
        #pragma unroll
        for (int bb = 0; bb < BT; bb++)
            #pragma unroll
            for (int d = 0; d < 8; d++) u[bb][d] = 0.f;
        #pragma unroll
        for (int i = 0; i < 8; i++) {
            const float* wp = &Wsh[tj * WSTR + i * 32 + m * 8];
            float4 wa = *reinterpret_cast<const float4*>(wp);
            float4 wb = *reinterpret_cast<const float4*>(wp + 4);
            float wr[8] = {wa.x, wa.y, wa.z, wa.w, wb.x, wb.y, wb.z, wb.w};
            #pragma unroll
            for (int bb = 0; bb < BT; bb++)
                #pragma unroll
                for (int d = 0; d < 8; d++)
                    u[bb][d] = fmaf(xv[bb][i], wr[d], u[bb][d]);
        }
        #pragma unroll
        for (int bb = 0; bb < BT; bb++)
            #pragma unroll
            for (int d = 0; d < 8; d++) sreg[bb][d] += u[bb][d];

        // ---- argmax_c <u, dc[c]> (strict > keeps first max, matches jnp.argmax) ----
        float best[BT]; int bc[BT];
        #pragma unroll
        for (int bb = 0; bb < BT; bb++) { best[bb] = -3.402823466e38f; bc[bb] = 0; }
        #pragma unroll
        for (int c = 0; c < 10; c++) {
            float4 da = *reinterpret_cast<const float4*>(&dcsh[c * 8]);
            float4 db = *reinterpret_cast<const float4*>(&dcsh[c * 8 + 4]);
            float dr[8] = {da.x, da.y, da.z, da.w, db.x, db.y, db.z, db.w};
            #pragma unroll
            for (int bb = 0; bb < BT; bb++) {
                float s = 0.f;
                #pragma unroll
                for (int d = 0; d < 8; d++) s = fmaf(u[bb][d], dr[d], s);
                if (s > best[bb]) { best[bb] = s; bc[bb] = c; }
            }
        }

        // ---- winner-gated accumulation into my private SMEM slice ----
        #pragma unroll
        for (int bb = 0; bb < BT; bb++) {
            float* p = myacc + bc[bb] * 8;
            float4 a0 = *reinterpret_cast<float4*>(p);
            float4 a1 = *reinterpret_cast<float4*>(p + 4);
            a0.x += u[bb][0]; a0.y += u[bb][1]; a0.z += u[bb][2]; a0.w += u[bb][3];
            a1.x += u[bb][4]; a1.y += u[bb][5]; a1.z += u[bb][6]; a1.w += u[bb][7];
            *reinterpret_cast<float4*>(p)     = a0;
            *reinterpret_cast<float4*>(p + 4) = a1;
            atomicAdd(&cntsh[wrp * 16 + bc[bb]], 1.f);
        }
    }

    // ---- S: reduce across the 4 j-lanes of each b-group, then 8 REDG ----
    #pragma unroll
    for (int bb = 0; bb < BT; bb++) {
        #pragma unroll
        for (int d = 0; d < 8; d++) {
            float v = sreg[bb][d];
            v += __shfl_xor_sync(0xFFFFFFFFu, v, 1);
            v += __shfl_xor_sync(0xFFFFFFFFu, v, 2);
            if (tj == 0) atomicAdd(&g_S[(bg * BT + bb) * 8 + d], v);
        }
    }

    __syncthreads();
    // ---- block-reduce the 128 seg slices (column t, conflict-free) ----
    if (t < 80) {
        float s0 = 0.f, s1 = 0.f, s2 = 0.f, s3 = 0.f;
        #pragma unroll 4
        for (int r = 0; r < TPB; r += 4) {
            s0 += acc[(r + 0) * ASTR + t];
            s1 += acc[(r + 1) * ASTR + t];
            s2 += acc[(r + 2) * ASTR + t];
            s3 += acc[(r + 3) * ASTR + t];
        }
        atomicAdd(&g_seg[t], (s0 + s1) + (s2 + s3));
    }
    if (t < 10) {
        float s = cntsh[t] + cntsh[16 + t] + cntsh[32 + t] + cntsh[48 + t];
        atomicAdd(&g_cnt[t], s);
    }
}

__global__ void finish_kernel(const float* __restrict__ dc,
                              float* __restrict__ out, int out_size)
{
    __shared__ float dcn[80];
    int t = threadIdx.x;
    if (t < 80) {
        int c = t >> 3;
        float d0 = dc[t];
        float v = d0 + (g_seg[t] - g_cnt[c] * d0) * (1.0f / 2359296.0f); // /(B*N)
        dcn[t] = v;
        if (out_size >= 1360) out[1280 + t] = v;   // (output, dc_new) concat
        if (out_size == 80)   out[t] = v;          // dc_new only (defensive)
    }
    __syncthreads();
    if (out_size >= 1280) {
        float sv[8];
        #pragma unroll
        for (int d = 0; d < 8; d++) sv[d] = g_S[t * 8 + d];
        #pragma unroll
        for (int c = 0; c < 10; c++) {
            float s = 0.f;
            #pragma unroll
            for (int d = 0; d < 8; d++) s = fmaf(sv[d], dcn[c * 8 + d], s);
            out[t * 10 + c] = s * (1.0f / 18432.0f);  // mean over N
        }
    }
}

extern "C" void kernel_launch(void* const* d_in, const int* in_sizes, int n_in,
                              void* d_out, int out_size)
{
    // Identify inputs by size (robust to metadata ordering):
    // x = 128*4608*8 = 4718592, W = 4608*8*32 = 1179648, dc = 80.
    const float* x  = nullptr;
    const float* W  = nullptr;
    const float* dc = nullptr;
    for (int i = 0; i < n_in; i++) {
        if (in_sizes[i] == 4718592)      x  = (const float*)d_in[i];
        else if (in_sizes[i] == 1179648) W  = (const float*)d_in[i];
        else if (in_sizes[i] == 80)      dc = (const float*)d_in[i];
    }
    if (!x)  x  = (const float*)d_in[0];
    if (!W)  W  = (const float*)d_in[1];
    if (!dc) dc = (const float*)d_in[2];
    float* out = (float*)d_out;

    zero_kernel<<<8, 128>>>();
    caps_kernel<<<NB, TPB>>>(x, W, dc);
    finish_kernel<<<1, 128>>>(dc, out, out_size);
}

// round 2
// speedup vs baseline: 1.1028x; 1.1028x over previous
#include <cuda_runtime.h>
#include <cstdint>

// DigitCaps fully-fused single kernel for GB300 (sm_103a).
// B=128, J=4608, INPUT_D=8, D=8, M=4, C=10, N=J*M=18432.
//
// Grid = 1152 blocks x 128 threads. Block owns JT=4 j's; each thread owns
// 1 j x 4 b's (16 votes). All heavy math in packed fp32x2 (fma.rn.f32x2).
// Global accumulators (zero at module load) gathered with atomics; the LAST
// block (ticket) computes dc_new + output and RESETS the accumulators so the
// kernel is deterministic across CUDA-graph replays.

#define J_TOTAL 4608
#define JT 4
#define TPB 128
#define NB (J_TOTAL / JT)
#define WSTR 264   // padded floats per j-row of W in smem (conflict-free)
#define ASTR 84    // padded per-thread seg-slice stride (80 used)

__device__ float g_S[1024];     // S[b*8+d] = sum_n u[b,n,d]
__device__ float g_seg[80];     // winner-gated sums [c*8+d]
__device__ float g_cnt[16];     // winner counts [c]
__device__ unsigned g_ticket;

// ---------- packed fp32x2 helpers (sm_103a) ----------
static __device__ __forceinline__ uint64_t pack2(float lo, float hi) {
    uint64_t r;
    asm("mov.b64 %0, {%1, %2};"
        : "=l"(r) : "r"(__float_as_uint(lo)), "r"(__float_as_uint(hi)));
    return r;
}
static __device__ __forceinline__ void unpack2(uint64_t v, float& lo, float& hi) {
    unsigned a, b;
    asm("mov.b64 {%0, %1}, %2;" : "=r"(a), "=r"(b) : "l"(v));
    lo = __uint_as_float(a); hi = __uint_as_float(b);
}
static __device__ __forceinline__ uint64_t fma2(uint64_t a, uint64_t b, uint64_t c) {
    uint64_t d;
    asm("fma.rn.f32x2 %0, %1, %2, %3;" : "=l"(d) : "l"(a), "l"(b), "l"(c));
    return d;
}
static __device__ __forceinline__ uint64_t mul2(uint64_t a, uint64_t b) {
    uint64_t d;
    asm("mul.rn.f32x2 %0, %1, %2;" : "=l"(d) : "l"(a), "l"(b));
    return d;
}
static __device__ __forceinline__ uint64_t add2(uint64_t a, uint64_t b) {
    uint64_t d;
    asm("add.rn.f32x2 %0, %1, %2;" : "=l"(d) : "l"(a), "l"(b));
    return d;
}
static __device__ __forceinline__ uint64_t shfl_xor64(uint64_t v, int m) {
    return (uint64_t)__shfl_xor_sync(0xFFFFFFFFu, (unsigned long long)v, m);
}

__global__ __launch_bounds__(TPB) void caps_kernel(
    const float* __restrict__ x,    // [B, J, 8]
    const float* __restrict__ Wg,   // [J, 8, 32]
    const float* __restrict__ dc,   // [10, 8]
    float* __restrict__ out, int out_size)
{
    __shared__ float Wsh[JT * WSTR];     //  4224 B
    __shared__ float acc[TPB * ASTR];    // 43008 B: per-thread seg slices
    __shared__ float dcsh[80];
    __shared__ float dcn[80];
    __shared__ unsigned s_last;

    const int t  = threadIdx.x;
    const int tj = t & 3;       // j within block
    const int bg = t >> 2;      // b-group (32 groups x 4 b)
    const int j  = blockIdx.x * JT + tj;

    // ---- cooperative W tile load (original [i][k] layout, padded rows) ----
    {
        const float4* src = reinterpret_cast<const float4*>(Wg)
                          + (size_t)blockIdx.x * (JT * 64);
        #pragma unroll
        for (int r = 0; r < 2; r++) {
            int g = t + r * TPB, jj = g >> 6, rem = g & 63;
            *reinterpret_cast<float4*>(&Wsh[jj * WSTR + rem * 4]) = src[g];
        }
    }
    if (t < 80) dcsh[t] = dc[t];
    float* myacc = &acc[t * ASTR];
    #pragma unroll
    for (int q = 0; q < 21; q++)
        reinterpret_cast<float4*>(myacc)[q] = make_float4(0.f, 0.f, 0.f, 0.f);
    __syncthreads();

    // ---- x for my 4 b's, duplicated into {x,x} packed regs ----
    uint64_t xd[4][8];
    #pragma unroll
    for (int bb = 0; bb < 4; bb++) {
        const float4* xp = reinterpret_cast<const float4*>(
            x + ((size_t)(bg * 4 + bb) * J_TOTAL + j) * 8);
        float4 a = xp[0], b = xp[1];
        xd[bb][0] = pack2(a.x, a.x); xd[bb][1] = pack2(a.y, a.y);
        xd[bb][2] = pack2(a.z, a.z); xd[bb][3] = pack2(a.w, a.w);
        xd[bb][4] = pack2(b.x, b.x); xd[bb][5] = pack2(b.y, b.y);
        xd[bb][6] = pack2(b.z, b.z); xd[bb][7] = pack2(b.w, b.w);
    }

    uint64_t sreg2[4][4];
    #pragma unroll
    for (int bb = 0; bb < 4; bb++)
        #pragma unroll
        for (int p = 0; p < 4; p++) sreg2[bb][p] = 0ull;
    uint64_t cnt64 = 0ull;

    #pragma unroll
    for (int m = 0; m < 4; m++) {
        // ---- u2[bb][p] = packed pair {u[2p], u[2p+1]} = x . W column-pairs ----
        uint64_t u2[4][4];
        #pragma unroll
        for (int bb = 0; bb < 4; bb++)
            #pragma unroll
            for (int p = 0; p < 4; p++) u2[bb][p] = 0ull;
        #pragma unroll
        for (int i = 0; i < 8; i++) {
            const ulonglong2* wp = reinterpret_cast<const ulonglong2*>(
                &Wsh[tj * WSTR + i * 32 + m * 8]);
            ulonglong2 wA = wp[0], wB = wp[1];
            #pragma unroll
            for (int bb = 0; bb < 4; bb++) {
                u2[bb][0] = fma2(xd[bb][i], wA.x, u2[bb][0]);
                u2[bb][1] = fma2(xd[bb][i], wA.y, u2[bb][1]);
                u2[bb][2] = fma2(xd[bb][i], wB.x, u2[bb][2]);
                u2[bb][3] = fma2(xd[bb][i], wB.y, u2[bb][3]);
            }
        }
        #pragma unroll
        for (int bb = 0; bb < 4; bb++)
            #pragma unroll
            for (int p = 0; p < 4; p++)
                sreg2[bb][p] = add2(sreg2[bb][p], u2[bb][p]);

        // ---- argmax_c <u, dc[c]> (strict >, first max, ascending c) ----
        float best[4]; int bc[4];
        #pragma unroll
        for (int bb = 0; bb < 4; bb++) { best[bb] = -3.402823466e38f; bc[bb] = 0; }
        #pragma unroll
        for (int c = 0; c < 10; c++) {
            const ulonglong2* dpp = reinterpret_cast<const ulonglong2*>(&dcsh[c * 8]);
            ulonglong2 dA = dpp[0], dB = dpp[1];
            #pragma unroll
            for (int bb = 0; bb < 4; bb++) {
                uint64_t s2 = mul2(u2[bb][0], dA.x);
                s2 = fma2(u2[bb][1], dA.y, s2);
                s2 = fma2(u2[bb][2], dB.x, s2);
                s2 = fma2(u2[bb][3], dB.y, s2);
                float lo, hi; unpack2(s2, lo, hi);
                float s = lo + hi;
                if (s > best[bb]) { best[bb] = s; bc[bb] = c; }
            }
        }

        // ---- winner-gated accumulation (packed RMW into private slice) ----
        #pragma unroll
        for (int bb = 0; bb < 4; bb++) {
            cnt64 += 1ull << (bc[bb] * 6);   // <=16 votes/class/thread: 6-bit fields
            ulonglong2* p2 = reinterpret_cast<ulonglong2*>(myacc + bc[bb] * 8);
            ulonglong2 a0 = p2[0], a1 = p2[1];
            a0.x = add2(a0.x, u2[bb][0]); a0.y = add2(a0.y, u2[bb][1]);
            a1.x = add2(a1.x, u2[bb][2]); a1.y = add2(a1.y, u2[bb][3]);
            p2[0] = a0; p2[1] = a1;
        }
    }

    // ---- S: reduce across the 4 j-lanes, then REDG ----
    #pragma unroll
    for (int bb = 0; bb < 4; bb++) {
        #pragma unroll
        for (int p = 0; p < 4; p++) {
            uint64_t v = sreg2[bb][p];
            v = add2(v, shfl_xor64(v, 1));
            v = add2(v, shfl_xor64(v, 2));
            if (tj == 0) {
                float lo, hi; unpack2(v, lo, hi);
                atomicAdd(&g_S[(bg * 4 + bb) * 8 + p * 2],     lo);
                atomicAdd(&g_S[(bg * 4 + bb) * 8 + p * 2 + 1], hi);
            }
        }
    }

    // ---- counts: warp REDUX per class, one REDG per warp ----
    {
        int lane = t & 31;
        #pragma unroll
        for (int c = 0; c < 10; c++) {
            unsigned v = (unsigned)((cnt64 >> (6 * c)) & 63ull);
            unsigned s = __reduce_add_sync(0xFFFFFFFFu, v);
            if (lane == 0) atomicAdd(&g_cnt[c], (float)s);
        }
    }

    __syncthreads();
    // ---- block-reduce seg slices (column t across 128 rows, conflict-free) ----
    if (t < 80) {
        float s0 = 0.f, s1 = 0.f, s2 = 0.f, s3 = 0.f;
        #pragma unroll 4
        for (int r = 0; r < TPB; r += 4) {
            s0 += acc[(r + 0) * ASTR + t];
            s1 += acc[(r + 1) * ASTR + t];
            s2 += acc[(r + 2) * ASTR + t];
            s3 += acc[(r + 3) * ASTR + t];
        }
        atomicAdd(&g_seg[t], (s0 + s1) + (s2 + s3));
    }

    // ---- last-block-done: finish + reset for next graph replay ----
    __threadfence();
    __syncthreads();
    if (t == 0) s_last = (atomicAdd(&g_ticket, 1u) == (unsigned)(NB - 1)) ? 1u : 0u;
    __syncthreads();
    if (!s_last) return;

    if (t < 80) {
        int c = t >> 3;
        float d0  = dc[t];
        float seg = __ldcg(&g_seg[t]);
        float cnt = __ldcg(&g_cnt[c]);
        float v = d0 + (seg - cnt * d0) * (1.0f / 2359296.0f);  // /(B*N)
        dcn[t] = v;
        if (out_size >= 1360) out[1280 + t] = v;   // (output, dc_new) concat
        if (out_size == 80)   out[t] = v;          // defensive
    }
    __syncthreads();
    if (out_size >= 1280) {
        float sv[8];
        #pragma unroll
        for (int d = 0; d < 8; d++) sv[d] = __ldcg(&g_S[t * 8 + d]);
        #pragma unroll
        for (int c = 0; c < 10; c++) {
            float s = 0.f;
            #pragma unroll
            for (int d = 0; d < 8; d++) s = fmaf(sv[d], dcn[c * 8 + d], s);
            out[t * 10 + c] = s * (1.0f / 18432.0f);   // mean over N
        }
    }
    // reset accumulators (each thread resets what it alone read/owns)
    #pragma unroll
    for (int d = 0; d < 8; d++) g_S[t * 8 + d] = 0.f;
    if (t < 80) g_seg[t] = 0.f;
    if (t < 16) g_cnt[t] = 0.f;
    if (t == 0) g_ticket = 0u;
}

extern "C" void kernel_launch(void* const* d_in, const int* in_sizes, int n_in,
                              void* d_out, int out_size)
{
    // Identify inputs by element count (robust to metadata ordering):
    // x = 128*4608*8 = 4718592, W = 4608*8*32 = 1179648, dc = 80.
    const float* x  = nullptr;
    const float* W  = nullptr;
    const float* dc = nullptr;
    for (int i = 0; i < n_in; i++) {
        if (in_sizes[i] == 4718592)      x  = (const float*)d_in[i];
        else if (in_sizes[i] == 1179648) W  = (const float*)d_in[i];
        else if (in_sizes[i] == 80)      dc = (const float*)d_in[i];
    }
    if (!x)  x  = (const float*)d_in[0];
    if (!W)  W  = (const float*)d_in[1];
    if (!dc) dc = (const float*)d_in[2];

    caps_kernel<<<NB, TPB>>>(x, W, dc, (float*)d_out, out_size);
}